// round 1
// baseline (speedup 1.0000x reference)
#include <cuda_runtime.h>

#define NN 100000
#define EE 3200000
#define DD 16
#define ATTN_SLOPE 0.2f
#define ACT_SLOPE 0.01f

// Scratch (device globals: allocation-free rule)
__device__ float g_featS[NN * DD];
__device__ float g_featD[NN * DD];
__device__ float g_accum[NN * DD];
__device__ float g_denom[NN];
__device__ float g_h2[NN * DD];

// ---------------------------------------------------------------------------
// Kernel 1: per-node linear transforms feat_src = h@Wsrc+bsrc, feat_dst = h@Wdst+bdst.
// Also zeroes the accumulators for the edge pass.
// h == nullptr means "read layer-1 output g_h2" (layer 2).
// ---------------------------------------------------------------------------
__global__ void __launch_bounds__(256) node_transform_kernel(
    const float* __restrict__ h,
    const float* __restrict__ Wsrc, const float* __restrict__ bsrc,
    const float* __restrict__ Wdst, const float* __restrict__ bdst,
    int n_nodes)
{
    __shared__ float sWs[DD * DD];
    __shared__ float sWd[DD * DD];
    __shared__ float sbs[DD];
    __shared__ float sbd[DD];

    int tid = threadIdx.x;
    if (tid < DD * DD) {
        sWs[tid] = Wsrc[tid];
        sWd[tid] = Wdst[tid];
    }
    if (tid < DD) {
        sbs[tid] = bsrc[tid];
        sbd[tid] = bdst[tid];
    }
    __syncthreads();

    int n = blockIdx.x * blockDim.x + tid;
    if (n >= n_nodes) return;

    const float* hrow = (h != nullptr) ? (h + (size_t)n * DD) : (g_h2 + (size_t)n * DD);
    const float4* hp = reinterpret_cast<const float4*>(hrow);
    float hv[DD];
    float4 t0 = hp[0], t1 = hp[1], t2 = hp[2], t3 = hp[3];
    hv[0]=t0.x; hv[1]=t0.y; hv[2]=t0.z;  hv[3]=t0.w;
    hv[4]=t1.x; hv[5]=t1.y; hv[6]=t1.z;  hv[7]=t1.w;
    hv[8]=t2.x; hv[9]=t2.y; hv[10]=t2.z; hv[11]=t2.w;
    hv[12]=t3.x; hv[13]=t3.y; hv[14]=t3.z; hv[15]=t3.w;

    float fs[DD], fd[DD];
#pragma unroll
    for (int j = 0; j < DD; j++) { fs[j] = sbs[j]; fd[j] = sbd[j]; }
#pragma unroll
    for (int i = 0; i < DD; i++) {
        float hi = hv[i];
#pragma unroll
        for (int j = 0; j < DD; j++) {
            fs[j] = fmaf(hi, sWs[i * DD + j], fs[j]);
            fd[j] = fmaf(hi, sWd[i * DD + j], fd[j]);
        }
    }

    float4* os = reinterpret_cast<float4*>(g_featS + (size_t)n * DD);
    float4* od = reinterpret_cast<float4*>(g_featD + (size_t)n * DD);
    float4* oa = reinterpret_cast<float4*>(g_accum + (size_t)n * DD);
#pragma unroll
    for (int q = 0; q < 4; q++) {
        os[q] = make_float4(fs[4*q], fs[4*q+1], fs[4*q+2], fs[4*q+3]);
        od[q] = make_float4(fd[4*q], fd[4*q+1], fd[4*q+2], fd[4*q+3]);
        oa[q] = make_float4(0.f, 0.f, 0.f, 0.f);
    }
    g_denom[n] = 0.f;
}

// ---------------------------------------------------------------------------
// Kernel 2: per-edge attention pass.
// score = attn . leaky_relu(featS[src] + featD[dst], 0.2); ex = exp(score)
// (segment-max subtraction skipped: softmax shift-invariance; |score| <~ 6)
// Accumulate ex*featS[src] and ex into dst accumulators via vector red ops.
// ---------------------------------------------------------------------------
__global__ void __launch_bounds__(256) edge_kernel(
    const int* __restrict__ src, const int* __restrict__ dst,
    const float* __restrict__ attn, int n_edges)
{
    __shared__ float sa[DD];
    if (threadIdx.x < DD) sa[threadIdx.x] = attn[threadIdx.x];
    __syncthreads();

    int e = blockIdx.x * blockDim.x + threadIdx.x;
    if (e >= n_edges) return;

    int s = src[e];
    int t = dst[e];

    const float4* fsp = reinterpret_cast<const float4*>(g_featS + (size_t)s * DD);
    const float4* fdp = reinterpret_cast<const float4*>(g_featD + (size_t)t * DD);

    float fa[DD], fb[DD];
    float4 a0 = fsp[0], a1 = fsp[1], a2 = fsp[2], a3 = fsp[3];
    float4 b0 = fdp[0], b1 = fdp[1], b2 = fdp[2], b3 = fdp[3];
    fa[0]=a0.x; fa[1]=a0.y; fa[2]=a0.z;  fa[3]=a0.w;
    fa[4]=a1.x; fa[5]=a1.y; fa[6]=a1.z;  fa[7]=a1.w;
    fa[8]=a2.x; fa[9]=a2.y; fa[10]=a2.z; fa[11]=a2.w;
    fa[12]=a3.x; fa[13]=a3.y; fa[14]=a3.z; fa[15]=a3.w;
    fb[0]=b0.x; fb[1]=b0.y; fb[2]=b0.z;  fb[3]=b0.w;
    fb[4]=b1.x; fb[5]=b1.y; fb[6]=b1.z;  fb[7]=b1.w;
    fb[8]=b2.x; fb[9]=b2.y; fb[10]=b2.z; fb[11]=b2.w;
    fb[12]=b3.x; fb[13]=b3.y; fb[14]=b3.z; fb[15]=b3.w;

    float sc = 0.f;
#pragma unroll
    for (int k = 0; k < DD; k++) {
        float x = fa[k] + fb[k];
        x = (x > 0.f) ? x : ATTN_SLOPE * x;
        sc = fmaf(sa[k], x, sc);
    }
    float ex = __expf(sc);

    float* ap = g_accum + (size_t)t * DD;
#pragma unroll
    for (int q = 0; q < 4; q++) {
        float v0 = ex * fa[4*q + 0];
        float v1 = ex * fa[4*q + 1];
        float v2 = ex * fa[4*q + 2];
        float v3 = ex * fa[4*q + 3];
        asm volatile("red.global.add.v4.f32 [%0], {%1, %2, %3, %4};"
                     :: "l"(ap + 4*q), "f"(v0), "f"(v1), "f"(v2), "f"(v3)
                     : "memory");
    }
    atomicAdd(&g_denom[t], ex);
}

// ---------------------------------------------------------------------------
// Kernel 3: per-node finalize: rst = accum/denom (0 for empty segments),
// then leaky_relu(0.01). Writes to g_h2 (layer 1) or to out (layer 2).
// ---------------------------------------------------------------------------
__global__ void __launch_bounds__(256) finalize_kernel(float* __restrict__ out,
                                                       int to_scratch, int n_nodes)
{
    int n = blockIdx.x * blockDim.x + threadIdx.x;
    if (n >= n_nodes) return;

    float dn = g_denom[n];
    float inv = (dn > 0.f) ? (1.0f / dn) : 0.0f;

    const float4* ap = reinterpret_cast<const float4*>(g_accum + (size_t)n * DD);
    float4* op = to_scratch
                     ? reinterpret_cast<float4*>(g_h2 + (size_t)n * DD)
                     : reinterpret_cast<float4*>(out + (size_t)n * DD);
#pragma unroll
    for (int q = 0; q < 4; q++) {
        float4 a = ap[q];
        float r0 = a.x * inv, r1 = a.y * inv, r2 = a.z * inv, r3 = a.w * inv;
        r0 = (r0 > 0.f) ? r0 : ACT_SLOPE * r0;
        r1 = (r1 > 0.f) ? r1 : ACT_SLOPE * r1;
        r2 = (r2 > 0.f) ? r2 : ACT_SLOPE * r2;
        r3 = (r3 > 0.f) ? r3 : ACT_SLOPE * r3;
        op[q] = make_float4(r0, r1, r2, r3);
    }
}

// ---------------------------------------------------------------------------
extern "C" void kernel_launch(void* const* d_in, const int* in_sizes, int n_in,
                              void* d_out, int out_size)
{
    const float* emb   = (const float*)d_in[0];
    const int*   src1  = (const int*)d_in[1];
    const int*   dst1  = (const int*)d_in[2];
    const int*   src2  = (const int*)d_in[3];
    const int*   dst2  = (const int*)d_in[4];
    const float* Wsrc1 = (const float*)d_in[5];
    const float* bsrc1 = (const float*)d_in[6];
    const float* Wdst1 = (const float*)d_in[7];
    const float* bdst1 = (const float*)d_in[8];
    const float* attn1 = (const float*)d_in[9];
    const float* Wsrc2 = (const float*)d_in[10];
    const float* bsrc2 = (const float*)d_in[11];
    const float* Wdst2 = (const float*)d_in[12];
    const float* bdst2 = (const float*)d_in[13];
    const float* attn2 = (const float*)d_in[14];

    int n_nodes = in_sizes[0] / DD;
    int n_edges1 = in_sizes[1];
    int n_edges2 = in_sizes[3];
    float* out = (float*)d_out;

    int nblk = (n_nodes + 255) / 256;
    int eblk1 = (n_edges1 + 255) / 256;
    int eblk2 = (n_edges2 + 255) / 256;

    // Layer 1
    node_transform_kernel<<<nblk, 256>>>(emb, Wsrc1, bsrc1, Wdst1, bdst1, n_nodes);
    edge_kernel<<<eblk1, 256>>>(src1, dst1, attn1, n_edges1);
    finalize_kernel<<<nblk, 256>>>(out, /*to_scratch=*/1, n_nodes);

    // Layer 2
    node_transform_kernel<<<nblk, 256>>>(nullptr, Wsrc2, bsrc2, Wdst2, bdst2, n_nodes);
    edge_kernel<<<eblk2, 256>>>(src2, dst2, attn2, n_edges2);
    finalize_kernel<<<nblk, 256>>>(out, /*to_scratch=*/0, n_nodes);
}